// round 15
// baseline (speedup 1.0000x reference)
#include <cuda_runtime.h>
#include <math_constants.h>

// RoIPool, warp-cooperative, single-pass row scan, float2 lanes, unroll-4
// pipeline, tail-split, STRENGTH-REDUCED refill addressing (chunk-level running
// pointer + immediate offsets; the refill clamp is provably dead in the main
// loop since k+4 < T implies h+4 <= hlast).
// feature [B,C,152,152] f32, rois [N,5] f32, out [N,C,7,7] f32.
// One warp = (roi n, 4 consecutive channels).
//   Columns: xs0 = xs & ~1, d = xs - xs0. Half-warp hw covers channels c0+hw
//   (A) and c0+2+hw (B); lane ln loads float2 at pair min(ln, plim),
//   plim=(d+roiw)>>1: every position phase 2 reads (d..d+roiw) is covered;
//   tail lanes duplicate the last pair (same cache lines, harmless for max).
//   Rows: scan ys..hlast = ys+ceil(7*binh)-1 once; bins tile with <=1-row
//   overlap; several bins may close on one row (do/while). 4-stage ring,
//   prefetch distance 4; main chunks refill unclamped via running pointer,
//   tail chunk (last <=4 stages) refill-free. Tail rows past hlast are clamped
//   preload duplicates that cannot close a bin (hcut <= hlast+1, ph<7 guard).
// Bin sizes = roiX * fl(1/7) (reciprocal multiply) to match XLA bit-exactly.

#define PH 7
#define PW 7
#define HF 152
#define WF 152
#define CPW 4
#define WARPS 8
#define CSI (HF * WF)          // channel stride in floats (int, compile-time)

__global__ __launch_bounds__(256) void roipool_f2s_kernel(
    const float* __restrict__ feat,
    const float* __restrict__ rois,
    const int* __restrict__ stride_p,
    float* __restrict__ out,
    int C, int gpr)
{
    __shared__ __align__(16) float rm[WARPS][CPW][PH][34];

    int si = *stride_p;
    float stride_f = (si > 0 && si <= 65536) ? (float)si : __int_as_float(si);
    const float scale = 1.0f / stride_f;

    const int warpId = threadIdx.x >> 5;
    const int lane   = threadIdx.x & 31;
    const int hw = lane >> 4;          // half-warp -> sub-channel
    const int ln = lane & 15;          // lane within half-warp -> column pair
    const int wg = blockIdx.x * WARPS + warpId;
    const int n  = wg / gpr;
    const int cg = wg - n * gpr;
    const int c0 = cg * CPW;

    const float* r = rois + n * 5;
    const int b  = (int)r[0];
    const int xs = (int)rintf(r[1] * scale);   // round-half-even, matches jnp.round
    const int ys = (int)rintf(r[2] * scale);
    const int xe = (int)rintf(r[3] * scale);
    const int ye = (int)rintf(r[4] * scale);
    const int roih = max(ye - ys + 1, 1);
    const int roiw = max(xe - xs + 1, 1);
    const float binh = (float)roih * (1.0f / 7.0f);   // reciprocal multiply (bit-exact)
    const float binw = (float)roiw * (1.0f / 7.0f);

    const int xs0 = xs & ~1;
    const int d   = xs - xs0;
    const int plim = (d + roiw) >> 1;           // last pair phase 2 can touch
    const int c2   = xs0 + 2 * min(ln, plim);   // in-bounds (<= 150)
    const bool wact = (ln <= plim);             // lane's pair readable by phase 2

    // base pointer for channel c0+hw; channel c0+2+hw at constant +2*CSI floats
    const float* fA = feat + ((size_t)(b * C + c0 + hw)) * (size_t)CSI + c2;

    const int hlast = ys + (int)ceilf(7.0f * binh) - 1;   // <= ye+1 <= 151
    int ph   = 0;
    int hcut = ys + (int)ceilf(binh);                     // hend of bin 0

    // 4-stage preload (row-clamped duplicates; harmless)
    float2 sA[4], sB[4];
    #pragma unroll
    for (int j = 0; j < 4; ++j) {
        const int hj = min(ys + j, hlast);
        sA[j] = *(const float2*)(fA + hj * WF);
        sB[j] = *(const float2*)(fA + hj * WF + 2 * CSI);
    }
    float2 mA = make_float2(-CUDART_INF_F, -CUDART_INF_F);
    float2 mB = make_float2(-CUDART_INF_F, -CUDART_INF_F);

    const int T = hlast - ys + 1;
    int k = 0;
    // running refill pointer: row ys+k+4 at each chunk start
    const float* pn = fA + (ys + 4) * WF;
    // ---- main chunks: refill unclamped (k+4 < T  =>  h+4 <= hlast) ----
    for (; k + 4 < T; k += 4) {
        #pragma unroll
        for (int j = 0; j < 4; ++j) {
            const int h = ys + k + j;
            const float2 aA = sA[j];
            const float2 aB = sB[j];
            // refill row h+4 = (chunk base)+j : immediate offsets off pn
            sA[j] = *(const float2*)(pn + j * WF);
            sB[j] = *(const float2*)(pn + j * WF + 2 * CSI);

            mA.x = fmaxf(mA.x, aA.x);  mA.y = fmaxf(mA.y, aA.y);
            mB.x = fmaxf(mB.x, aB.x);  mB.y = fmaxf(mB.y, aB.y);

            if (ph < PH && h == hcut - 1) {    // warp-uniform; may close SEVERAL bins
                do {
                    if (wact) {
                        const int p = 2 * ln;
                        *(float2*)&rm[warpId][hw][ph][p]     = mA;
                        *(float2*)&rm[warpId][2 + hw][ph][p] = mB;
                    }
                    const int hs_next = ys + (int)floorf((float)(ph + 1) * binh);
                    const bool ov = (hs_next <= h);
                    mA.x = ov ? aA.x : -CUDART_INF_F;
                    mA.y = ov ? aA.y : -CUDART_INF_F;
                    mB.x = ov ? aB.x : -CUDART_INF_F;
                    mB.y = ov ? aB.y : -CUDART_INF_F;
                    ph++;
                    hcut = ys + (int)ceilf((float)(ph + 1) * binh);
                } while (ph < PH && h == hcut - 1);
            }
        }
        pn += 4 * WF;
    }
    // ---- tail chunk: consume remaining stages, NO refills ----
    #pragma unroll
    for (int j = 0; j < 4; ++j) {
        const int h = ys + k + j;            // may exceed hlast: dupes, cannot close
        const float2 aA = sA[j];
        const float2 aB = sB[j];

        mA.x = fmaxf(mA.x, aA.x);  mA.y = fmaxf(mA.y, aA.y);
        mB.x = fmaxf(mB.x, aB.x);  mB.y = fmaxf(mB.y, aB.y);

        if (ph < PH && h == hcut - 1) {
            do {
                if (wact) {
                    const int p = 2 * ln;
                    *(float2*)&rm[warpId][hw][ph][p]     = mA;
                    *(float2*)&rm[warpId][2 + hw][ph][p] = mB;
                }
                const int hs_next = ys + (int)floorf((float)(ph + 1) * binh);
                const bool ov = (hs_next <= h);
                mA.x = ov ? aA.x : -CUDART_INF_F;
                mA.y = ov ? aA.y : -CUDART_INF_F;
                mB.x = ov ? aB.x : -CUDART_INF_F;
                mB.y = ov ? aB.y : -CUDART_INF_F;
                ph++;
                hcut = ys + (int)ceilf((float)(ph + 1) * binh);
            } while (ph < PH && h == hcut - 1);
        }
    }
    __syncwarp();

    // ---- phase 2: column max per (ph,pw) bin (positions offset by d) ----
    // Warp-uniform depth J; extra iterations clamp to wl (broadcast dupes).
    const int J = min((int)ceilf(binw) + 1, 6);
    const size_t obase = ((size_t)n * C + c0) * (PH * PW);
    #pragma unroll
    for (int rep = 0; rep < 2; ++rep) {
        int pp = rep * 32 + lane;
        if (pp < PH * PW) {
            int phh = pp / PW;
            int pw  = pp - phh * PW;
            int wsl = (int)floorf((float)pw * binw);          // local cols, >= 0
            int wel = (int)ceilf((float)(pw + 1) * binw);     // may reach roiw+1
            const int wl = wel - 1;                           // <= roiw (covered)
            float v0 = -CUDART_INF_F, v1 = -CUDART_INF_F;
            float v2 = -CUDART_INF_F, v3 = -CUDART_INF_F;
            for (int j = 0; j < J; ++j) {                     // warp-uniform trip
                const int idx = d + min(wsl + j, wl);
                v0 = fmaxf(v0, rm[warpId][0][phh][idx]);
                v1 = fmaxf(v1, rm[warpId][1][phh][idx]);
                v2 = fmaxf(v2, rm[warpId][2][phh][idx]);
                v3 = fmaxf(v3, rm[warpId][3][phh][idx]);
            }
            out[obase + pp]                 = v0;
            out[obase + (PH * PW) + pp]     = v1;
            out[obase + 2 * (PH * PW) + pp] = v2;
            out[obase + 3 * (PH * PW) + pp] = v3;
        }
    }
}

extern "C" void kernel_launch(void* const* d_in, const int* in_sizes, int n_in,
                              void* d_out, int out_size) {
    const float* feat   = (const float*)d_in[0];
    const float* rois   = (const float*)d_in[1];
    const int*   stride = (const int*)d_in[2];
    float*       out    = (float*)d_out;

    const int N = in_sizes[1] / 5;
    const int C = out_size / (N * PH * PW);        // 256
    const int gpr = C / CPW;                       // 64
    const int total_warps = N * gpr;               // 32768
    const int blocks = (total_warps + WARPS - 1) / WARPS;   // 4096

    roipool_f2s_kernel<<<blocks, 32 * WARPS>>>(feat, rois, stride, out, C, gpr);
}

// round 16
// speedup vs baseline: 1.4306x; 1.4306x over previous
#include <cuda_runtime.h>
#include <math_constants.h>

// RoIPool, warp-cooperative, single-pass row scan, float2 lanes, unroll-4
// pipeline, tail-split, strength-reduced refills via TWO running pointers
// (pA, pB advance 4*WF per chunk; refill offsets j*WF = 2432j bytes are
// LDG-immediate-encodable — the R15 regression came from a 184KB offset that
// forced per-load 64-bit adds).
// feature [B,C,152,152] f32, rois [N,5] f32, out [N,C,7,7] f32.
// One warp = (roi n, 4 consecutive channels).
//   Columns: xs0 = xs & ~1, d = xs - xs0. Half-warp hw covers channels c0+hw
//   (A) and c0+2+hw (B); lane ln loads float2 at pair min(ln, plim),
//   plim=(d+roiw)>>1: every position phase 2 reads (d..d+roiw) is covered;
//   tail lanes duplicate the last pair (same cache lines, harmless for max).
//   Rows: scan ys..hlast = ys+ceil(7*binh)-1 once; bins tile with <=1-row
//   overlap; several bins may close on one row (do/while). 4-stage ring,
//   prefetch distance 4; main chunks refill unclamped (k+4 < T => h+4 <=
//   hlast); tail chunk (last <=4 stages) refill-free. Tail rows past hlast
//   are clamped preload duplicates that cannot close a bin (hcut <= hlast+1,
//   ph<7 guard).
// Bin sizes = roiX * fl(1/7) (reciprocal multiply) to match XLA bit-exactly.

#define PH 7
#define PW 7
#define HF 152
#define WF 152
#define CPW 4
#define WARPS 8

__global__ __launch_bounds__(256) void roipool_f2r_kernel(
    const float* __restrict__ feat,
    const float* __restrict__ rois,
    const int* __restrict__ stride_p,
    float* __restrict__ out,
    int C, int gpr)
{
    __shared__ __align__(16) float rm[WARPS][CPW][PH][34];

    int si = *stride_p;
    float stride_f = (si > 0 && si <= 65536) ? (float)si : __int_as_float(si);
    const float scale = 1.0f / stride_f;

    const int warpId = threadIdx.x >> 5;
    const int lane   = threadIdx.x & 31;
    const int hw = lane >> 4;          // half-warp -> sub-channel
    const int ln = lane & 15;          // lane within half-warp -> column pair
    const int wg = blockIdx.x * WARPS + warpId;
    const int n  = wg / gpr;
    const int cg = wg - n * gpr;
    const int c0 = cg * CPW;

    const float* r = rois + n * 5;
    const int b  = (int)r[0];
    const int xs = (int)rintf(r[1] * scale);   // round-half-even, matches jnp.round
    const int ys = (int)rintf(r[2] * scale);
    const int xe = (int)rintf(r[3] * scale);
    const int ye = (int)rintf(r[4] * scale);
    const int roih = max(ye - ys + 1, 1);
    const int roiw = max(xe - xs + 1, 1);
    const float binh = (float)roih * (1.0f / 7.0f);   // reciprocal multiply (bit-exact)
    const float binw = (float)roiw * (1.0f / 7.0f);

    const int xs0 = xs & ~1;
    const int d   = xs - xs0;
    const int plim = (d + roiw) >> 1;           // last pair phase 2 can touch
    const int c2   = xs0 + 2 * min(ln, plim);   // in-bounds (<= 150)
    const bool wact = (ln <= plim);             // lane's pair readable by phase 2

    const size_t cs = (size_t)HF * WF;
    const float* fA = feat + ((size_t)(b * C + c0 + hw)) * cs + c2;  // ch c0+hw
    const float* fB = fA + 2 * cs;                                    // ch c0+2+hw

    const int hlast = ys + (int)ceilf(7.0f * binh) - 1;   // <= ye+1 <= 151
    int ph   = 0;
    int hcut = ys + (int)ceilf(binh);                     // hend of bin 0

    // 4-stage preload (row-clamped duplicates; harmless)
    float2 sA[4], sB[4];
    #pragma unroll
    for (int j = 0; j < 4; ++j) {
        const int hj = min(ys + j, hlast);
        sA[j] = *(const float2*)(fA + hj * WF);
        sB[j] = *(const float2*)(fB + hj * WF);
    }
    float2 mA = make_float2(-CUDART_INF_F, -CUDART_INF_F);
    float2 mB = make_float2(-CUDART_INF_F, -CUDART_INF_F);

    const int T = hlast - ys + 1;
    int k = 0;
    // running refill pointers: row ys+k+4 at each chunk start
    const float* pA = fA + (ys + 4) * WF;
    const float* pB = fB + (ys + 4) * WF;
    // ---- main chunks: refill unclamped (k+4 < T  =>  h+4 <= hlast) ----
    for (; k + 4 < T; k += 4) {
        #pragma unroll
        for (int j = 0; j < 4; ++j) {
            const int h = ys + k + j;
            const float2 aA = sA[j];
            const float2 aB = sB[j];
            // refill row h+4: small immediate offsets off running pointers
            sA[j] = *(const float2*)(pA + j * WF);
            sB[j] = *(const float2*)(pB + j * WF);

            mA.x = fmaxf(mA.x, aA.x);  mA.y = fmaxf(mA.y, aA.y);
            mB.x = fmaxf(mB.x, aB.x);  mB.y = fmaxf(mB.y, aB.y);

            if (ph < PH && h == hcut - 1) {    // warp-uniform; may close SEVERAL bins
                do {
                    if (wact) {
                        const int p = 2 * ln;
                        *(float2*)&rm[warpId][hw][ph][p]     = mA;
                        *(float2*)&rm[warpId][2 + hw][ph][p] = mB;
                    }
                    const int hs_next = ys + (int)floorf((float)(ph + 1) * binh);
                    const bool ov = (hs_next <= h);
                    mA.x = ov ? aA.x : -CUDART_INF_F;
                    mA.y = ov ? aA.y : -CUDART_INF_F;
                    mB.x = ov ? aB.x : -CUDART_INF_F;
                    mB.y = ov ? aB.y : -CUDART_INF_F;
                    ph++;
                    hcut = ys + (int)ceilf((float)(ph + 1) * binh);
                } while (ph < PH && h == hcut - 1);
            }
        }
        pA += 4 * WF;
        pB += 4 * WF;
    }
    // ---- tail chunk: consume remaining stages, NO refills ----
    #pragma unroll
    for (int j = 0; j < 4; ++j) {
        const int h = ys + k + j;            // may exceed hlast: dupes, cannot close
        const float2 aA = sA[j];
        const float2 aB = sB[j];

        mA.x = fmaxf(mA.x, aA.x);  mA.y = fmaxf(mA.y, aA.y);
        mB.x = fmaxf(mB.x, aB.x);  mB.y = fmaxf(mB.y, aB.y);

        if (ph < PH && h == hcut - 1) {
            do {
                if (wact) {
                    const int p = 2 * ln;
                    *(float2*)&rm[warpId][hw][ph][p]     = mA;
                    *(float2*)&rm[warpId][2 + hw][ph][p] = mB;
                }
                const int hs_next = ys + (int)floorf((float)(ph + 1) * binh);
                const bool ov = (hs_next <= h);
                mA.x = ov ? aA.x : -CUDART_INF_F;
                mA.y = ov ? aA.y : -CUDART_INF_F;
                mB.x = ov ? aB.x : -CUDART_INF_F;
                mB.y = ov ? aB.y : -CUDART_INF_F;
                ph++;
                hcut = ys + (int)ceilf((float)(ph + 1) * binh);
            } while (ph < PH && h == hcut - 1);
        }
    }
    __syncwarp();

    // ---- phase 2: column max per (ph,pw) bin (positions offset by d) ----
    // Warp-uniform depth J; extra iterations clamp to wl (broadcast dupes).
    const int J = min((int)ceilf(binw) + 1, 6);
    const size_t obase = ((size_t)n * C + c0) * (PH * PW);
    #pragma unroll
    for (int rep = 0; rep < 2; ++rep) {
        int pp = rep * 32 + lane;
        if (pp < PH * PW) {
            int phh = pp / PW;
            int pw  = pp - phh * PW;
            int wsl = (int)floorf((float)pw * binw);          // local cols, >= 0
            int wel = (int)ceilf((float)(pw + 1) * binw);     // may reach roiw+1
            const int wl = wel - 1;                           // <= roiw (covered)
            float v0 = -CUDART_INF_F, v1 = -CUDART_INF_F;
            float v2 = -CUDART_INF_F, v3 = -CUDART_INF_F;
            for (int j = 0; j < J; ++j) {                     // warp-uniform trip
                const int idx = d + min(wsl + j, wl);
                v0 = fmaxf(v0, rm[warpId][0][phh][idx]);
                v1 = fmaxf(v1, rm[warpId][1][phh][idx]);
                v2 = fmaxf(v2, rm[warpId][2][phh][idx]);
                v3 = fmaxf(v3, rm[warpId][3][phh][idx]);
            }
            out[obase + pp]                 = v0;
            out[obase + (PH * PW) + pp]     = v1;
            out[obase + 2 * (PH * PW) + pp] = v2;
            out[obase + 3 * (PH * PW) + pp] = v3;
        }
    }
}

extern "C" void kernel_launch(void* const* d_in, const int* in_sizes, int n_in,
                              void* d_out, int out_size) {
    const float* feat   = (const float*)d_in[0];
    const float* rois   = (const float*)d_in[1];
    const int*   stride = (const int*)d_in[2];
    float*       out    = (float*)d_out;

    const int N = in_sizes[1] / 5;
    const int C = out_size / (N * PH * PW);        // 256
    const int gpr = C / CPW;                       // 64
    const int total_warps = N * gpr;               // 32768
    const int blocks = (total_warps + WARPS - 1) / WARPS;   // 4096

    roipool_f2r_kernel<<<blocks, 32 * WARPS>>>(feat, rois, stride, out, C, gpr);
}